// round 10
// baseline (speedup 1.0000x reference)
#include <cuda_runtime.h>
#include <cuda_bf16.h>
#include <cstdint>

// Problem constants (fixed by the dataset)
#define T_TOK   16384
#define N_EXP   16
#define DIM     2048
#define CAP     2048
#define SLOTS   (N_EXP * CAP)           // 32768
#define OUT_MAIN ((size_t)SLOTS * DIM)  // 67,108,864 floats
#define ROW4    (DIM / 4)               // 512 float4 per row

#define CHUNKS  64
#define CHTOK   256                     // tokens per index chunk (== blockDim)
#define FILLB   (N_EXP * 8)             // 128 fill helper blocks in scatter grid

// Device scratch (no allocs allowed)
__device__ int   g_cnt[N_EXP * CHUNKS];   // per-expert per-chunk hit counts
__device__ int   g_load[N_EXP];           // capacity-clipped loads
__device__ int   g_dst[T_TOK * 2];        // per-token destination slots (-1 = dropped)
__device__ float g_gt [T_TOK * 2];        // per-token gate scores
__device__ unsigned g_arrive;             // phase-tagged arrive counter (see below)

// ---------------------------------------------------------------------------
// Kernel 1: fused count + scan + dest. 64 blocks x 256 threads.
// All 64 blocks are guaranteed co-resident (64 < 148 SMs, occupancy >= 1),
// so the internal spin barrier cannot deadlock.
//
// The barrier counter is phase-tagged instead of reset: each graph replay
// adds exactly 2*CHUNKS arrivals, so the k-th replay waits for the running
// total to reach its own phase target. No reset kernel, fully deterministic
// under graph replay... except the counter must not survive FOREVER — we
// let it wrap naturally (unsigned), and targets are computed from the value
// read at block start, which is a multiple of CHUNKS between replays.
// Simpler and airtight: each block reads the counter BEFORE arriving; the
// base is identical across blocks only if replays don't overlap — they
// don't (graph replays are serialized on one stream). To avoid any base-
// disagreement hazard we instead reset the counter at the END of the
// barrier use: the last block to pass phase 1 resets it to 0 after phase-2
// data is published. Since there is only ONE barrier phase here, we use:
// arrive -> spin to CHUNKS -> (everyone past) -> one elected block sets 0.
// The reset block is the LAST to arrive (its atomicAdd returned CHUNKS-1),
// and it resets only after it has also passed the spin, i.e. after all
// blocks arrived. Blocks still spinning see either CHUNKS or 0... 0 would
// hang them. So the reset must happen only after all blocks have LEFT the
// spin. Second counter: g_arrive counts arrivals, blocks spin on it, then
// each block atomically increments the SAME counter's high half on exit;
// the block that observes high == CHUNKS resets the whole word. High-half
// increments only happen after low reached CHUNKS, so no spinner can be
// stranded: by then every spinner has already seen low==CHUNKS (low half
// is never decreased before the full reset, and the reset happens after
// ALL blocks incremented high, i.e. all are past the spin).
// ---------------------------------------------------------------------------
__global__ __launch_bounds__(CHTOK, 1)
void idx_kernel(const int4* __restrict__ hm4, const float4* __restrict__ sc4,
                float* __restrict__ out, long long out_size)
{
    const int c    = blockIdx.x;
    const int tid  = threadIdx.x;
    const int lane = tid & 31;
    const int wid  = tid >> 5;            // 0..7
    const int t    = c * CHTOK + tid;
    const unsigned lt = (1u << lane) - 1u;

    int4   m[4];
    float4 s[4];
    #pragma unroll
    for (int i = 0; i < 4; i++) {
        m[i] = hm4[(size_t)t * 4 + i];
        s[i] = sc4[(size_t)t * 4 + i];
    }
    const int*   v  = (const int*)m;
    const float* sv = (const float*)s;

    unsigned bits = 0;
    #pragma unroll
    for (int e = 0; e < N_EXP; e++) bits |= (v[e] > 0 ? 1u : 0u) << e;

    __shared__ int s_cnt[8][N_EXP];
    __shared__ int s_off[N_EXP];

    int      k = 0;
    int      e_sel[2] = {-1, -1};
    unsigned b_sel[2] = {0, 0};
    #pragma unroll
    for (int e = 0; e < N_EXP; e++) {
        unsigned ball = __ballot_sync(0xffffffffu, (bits >> e) & 1u);
        if (lane == 0) s_cnt[wid][e] = __popc(ball);
        if (((bits >> e) & 1u) && k < 2) { e_sel[k] = e; b_sel[k] = ball; k++; }
    }
    __syncthreads();

    if (tid < N_EXP) {
        int sum = 0;
        #pragma unroll
        for (int w = 0; w < 8; w++) sum += s_cnt[w][tid];
        g_cnt[tid * CHUNKS + c] = sum;
    }
    __threadfence();
    __syncthreads();

    // ---- co-resident barrier: low 16 bits = arrivals, high 16 = departures.
    if (tid == 0) {
        atomicAdd(&g_arrive, 1u);                       // arrive (low half)
        volatile unsigned* p = &g_arrive;
        while ((*p & 0xFFFFu) < CHUNKS) { }             // spin: all arrived
        unsigned prev = atomicAdd(&g_arrive, 0x10000u); // depart (high half)
        if ((prev >> 16) == CHUNKS - 1)                 // last one out:
            atomicExch(&g_arrive, 0u);                  //   reset for next replay
    }
    __syncthreads();

    // exclusive chunk offsets: expert = tid>>4, segment = tid&15 (4 chunks each)
    {
        const int e   = tid >> 4;
        const int seg = tid & 15;
        int partial = 0;
        #pragma unroll
        for (int i = 0; i < 4; i++) {
            const int cc = seg * 4 + i;
            if (cc < c) partial += __ldcg(&g_cnt[e * CHUNKS + cc]);
        }
        #pragma unroll
        for (int o = 8; o >= 1; o >>= 1)
            partial += __shfl_down_sync(0xffffffffu, partial, o, 16);
        if (seg == 0) s_off[e] = partial;
    }
    __syncthreads();

    // last chunk block owns the totals -> loads
    if (c == CHUNKS - 1 && tid < N_EXP) {
        int tot = s_off[tid];
        #pragma unroll
        for (int w = 0; w < 8; w++) tot += s_cnt[w][tid];
        const int load = tot < CAP ? tot : CAP;
        g_load[tid] = load;
        if (out_size >= (long long)(OUT_MAIN + N_EXP))
            out[OUT_MAIN + tid] = (float)load;
    }

    // per-token destinations
    #pragma unroll
    for (int j = 0; j < 2; j++) {
        int dst = -1;
        float g = 0.0f;
        if (j < k) {
            const int e = e_sel[j];
            int woff = 0;
            #pragma unroll
            for (int w = 0; w < 8; w++) if (w < wid) woff += s_cnt[w][e];
            const int pos = s_off[e] + woff + __popc(b_sel[j] & lt);
            if (pos < CAP) dst = e * CAP + pos;
            g = sv[e];
        }
        g_dst[t * 2 + j] = dst;
        g_gt [t * 2 + j] = g;
    }
}

// ---------------------------------------------------------------------------
// Kernel 2: fused fill + token-major scatter (proven R8 design).
// Blocks [0, FILLB): zero-fill expert tails [load_e, CAP).
// Blocks [FILLB, ...): read token row once, write <=2 destination rows.
// ---------------------------------------------------------------------------
__global__ __launch_bounds__(256, 8)
void scatter_kernel(const float4* __restrict__ in_flow, float4* __restrict__ out)
{
    const int tid = threadIdx.x;

    if (blockIdx.x < FILLB) {
        const int f = blockIdx.x;
        const int e = f >> 3;
        const int y = f & 7;
        const float4 z = make_float4(0.f, 0.f, 0.f, 0.f);
        const int load = g_load[e];
        for (int r = load + y; r < CAP; r += 8) {
            float4* o = out + (size_t)(e * CAP + r) * ROW4;
            __stcs(o + tid, z);
            __stcs(o + tid + 256, z);
        }
        return;
    }

    const int t = blockIdx.x - FILLB;

    const int d0 = g_dst[t * 2 + 0];
    const int d1 = g_dst[t * 2 + 1];
    if (d0 < 0 && d1 < 0) return;

    const float g0 = g_gt[t * 2 + 0];
    const float g1 = g_gt[t * 2 + 1];

    const float4* __restrict__ r = in_flow + (size_t)t * ROW4;
    float4 a = __ldcs(r + tid);
    float4 b = __ldcs(r + tid + 256);

    if (d0 >= 0) {
        float4* o = out + (size_t)d0 * ROW4;
        __stcs(o + tid,       make_float4(a.x * g0, a.y * g0, a.z * g0, a.w * g0));
        __stcs(o + tid + 256, make_float4(b.x * g0, b.y * g0, b.z * g0, b.w * g0));
    }
    if (d1 >= 0) {
        float4* o = out + (size_t)d1 * ROW4;
        __stcs(o + tid,       make_float4(a.x * g1, a.y * g1, a.z * g1, a.w * g1));
        __stcs(o + tid + 256, make_float4(b.x * g1, b.y * g1, b.z * g1, b.w * g1));
    }
}

extern "C" void kernel_launch(void* const* d_in, const int* in_sizes, int n_in,
                              void* d_out, int out_size)
{
    const float* in_flow  = (const float*)d_in[0];   // [T, D] f32
    const int*   hot_mask = (const int*)  d_in[1];   // [T, E] i32
    const float* score    = (const float*)d_in[2];   // [T, E] f32
    float*       out      = (float*)d_out;

    idx_kernel<<<CHUNKS, CHTOK>>>((const int4*)hot_mask, (const float4*)score,
                                  out, (long long)out_size);
    scatter_kernel<<<T_TOK + FILLB, 256>>>((const float4*)in_flow, (float4*)out);
}